// round 1
// baseline (speedup 1.0000x reference)
#include <cuda_runtime.h>
#include <math.h>

#define NTOK 4096
#define DIM  1024

// Scratch (allocation-free rule: __device__ globals)
__device__ float g_q [NTOK * DIM];            // Q  [N, D]
__device__ float g_k [NTOK * DIM];            // K  [N, D]
__device__ float g_vt[DIM * NTOK];            // V^T [D, N]
__device__ float g_s [(size_t)NTOK * NTOK];   // scores / probs [N, N]

// ---------------------------------------------------------------------------
// GEMM-NT: C[M,N] = A[M,K] @ B[N,K]^T   (both operands K-inner, row-major)
// BM=BN=128, BK=8, 256 threads, 8x8 per-thread register tile.
// TRANS_OUT: store C transposed as [N, M] (used to produce V^T directly).
// All problem dims are multiples of 128 -> no boundary checks.
// ---------------------------------------------------------------------------
template <bool TRANS_OUT>
__global__ __launch_bounds__(256)
void gemm_nt_kernel(const float* __restrict__ A,
                    const float* __restrict__ B,
                    float* __restrict__ C,
                    int M, int N, int K)
{
    __shared__ float As[8][128];
    __shared__ float Bs[8][128];

    const int m0 = blockIdx.y * 128;
    const int n0 = blockIdx.x * 128;
    const int tid = threadIdx.x;

    // Global->shared load mapping: each thread loads one float4 from A and B.
    const int lrow = tid >> 1;          // 0..127
    const int lcol = (tid & 1) * 4;     // 0 or 4
    const float* Aptr = A + (size_t)(m0 + lrow) * K + lcol;
    const float* Bptr = B + (size_t)(n0 + lrow) * K + lcol;

    // Compute mapping: 16x16 thread grid, each thread owns an 8x8 C tile.
    const int tm = (tid >> 4) * 8;      // 0..120
    const int tn = (tid & 15) * 8;      // 0..120

    float acc[8][8];
#pragma unroll
    for (int i = 0; i < 8; i++)
#pragma unroll
        for (int j = 0; j < 8; j++)
            acc[i][j] = 0.0f;

    for (int k0 = 0; k0 < K; k0 += 8) {
        float4 av = *(const float4*)(Aptr + k0);
        float4 bv = *(const float4*)(Bptr + k0);

        __syncthreads();   // protect previous iteration's reads
        As[lcol + 0][lrow] = av.x;
        As[lcol + 1][lrow] = av.y;
        As[lcol + 2][lrow] = av.z;
        As[lcol + 3][lrow] = av.w;
        Bs[lcol + 0][lrow] = bv.x;
        Bs[lcol + 1][lrow] = bv.y;
        Bs[lcol + 2][lrow] = bv.z;
        Bs[lcol + 3][lrow] = bv.w;
        __syncthreads();

#pragma unroll
        for (int kk = 0; kk < 8; kk++) {
            float a[8], b[8];
#pragma unroll
            for (int i = 0; i < 8; i++) a[i] = As[kk][tm + i];
#pragma unroll
            for (int j = 0; j < 8; j++) b[j] = Bs[kk][tn + j];
#pragma unroll
            for (int i = 0; i < 8; i++)
#pragma unroll
                for (int j = 0; j < 8; j++)
                    acc[i][j] = fmaf(a[i], b[j], acc[i][j]);
        }
    }

    if (TRANS_OUT) {
#pragma unroll
        for (int j = 0; j < 8; j++)
#pragma unroll
            for (int i = 0; i < 8; i++)
                C[(size_t)(n0 + tn + j) * M + (m0 + tm + i)] = acc[i][j];
    } else {
#pragma unroll
        for (int i = 0; i < 8; i++) {
            float4* crow = (float4*)(C + (size_t)(m0 + tm + i) * N + n0 + tn);
            crow[0] = make_float4(acc[i][0], acc[i][1], acc[i][2], acc[i][3]);
            crow[1] = make_float4(acc[i][4], acc[i][5], acc[i][6], acc[i][7]);
        }
    }
}

// ---------------------------------------------------------------------------
// Row softmax over S[N, N] in place, with the 1/sqrt(D)=1/32 scale folded in:
// softmax(s/32)_i = exp((s_i - max)/32) / sum_j exp((s_j - max)/32)
// One 256-thread block per row.
// ---------------------------------------------------------------------------
__global__ __launch_bounds__(256)
void softmax_rows_kernel(float* __restrict__ S)
{
    const int row = blockIdx.x;
    float* p = S + (size_t)row * NTOK;
    const int tid = threadIdx.x;
    __shared__ float red[256];

    // 1) row max
    float m = -INFINITY;
    for (int i = tid; i < NTOK; i += 256) m = fmaxf(m, p[i]);
    red[tid] = m;
    __syncthreads();
    for (int s = 128; s > 0; s >>= 1) {
        if (tid < s) red[tid] = fmaxf(red[tid], red[tid + s]);
        __syncthreads();
    }
    m = red[0];
    __syncthreads();

    // 2) exp + sum
    const float scale = 0.03125f;  // 1/32
    float sum = 0.0f;
    for (int i = tid; i < NTOK; i += 256) {
        float e = __expf((p[i] - m) * scale);
        p[i] = e;
        sum += e;
    }
    red[tid] = sum;
    __syncthreads();
    for (int s = 128; s > 0; s >>= 1) {
        if (tid < s) red[tid] += red[tid + s];
        __syncthreads();
    }
    const float inv = 1.0f / red[0];
    __syncthreads();

    // 3) normalize
    for (int i = tid; i < NTOK; i += 256) p[i] *= inv;
}

// ---------------------------------------------------------------------------
// Launch: Q = X Wq^T, K = X Wk^T, V^T = (X Wv^T)^T,
//         S = Q K^T, softmax(S/32), O = S V  (== S @ (V^T)^T, GEMM-NT)
// ---------------------------------------------------------------------------
extern "C" void kernel_launch(void* const* d_in, const int* in_sizes, int n_in,
                              void* d_out, int out_size)
{
    const float* x  = (const float*)d_in[0];
    const float* wq = (const float*)d_in[1];
    const float* wk = (const float*)d_in[2];
    const float* wv = (const float*)d_in[3];
    float* out = (float*)d_out;

    float *q, *k, *vt, *s;
    cudaGetSymbolAddress((void**)&q,  g_q);
    cudaGetSymbolAddress((void**)&k,  g_k);
    cudaGetSymbolAddress((void**)&vt, g_vt);
    cudaGetSymbolAddress((void**)&s,  g_s);

    dim3 thr(256);
    dim3 grid_proj(DIM / 128, NTOK / 128);    // (8, 32)
    dim3 grid_sc(NTOK / 128, NTOK / 128);     // (32, 32)

    // Projections
    gemm_nt_kernel<false><<<grid_proj, thr>>>(x, wq, q,  NTOK, DIM, DIM);
    gemm_nt_kernel<false><<<grid_proj, thr>>>(x, wk, k,  NTOK, DIM, DIM);
    gemm_nt_kernel<true ><<<grid_proj, thr>>>(x, wv, vt, NTOK, DIM, DIM);

    // Scores S = Q K^T
    gemm_nt_kernel<false><<<grid_sc, thr>>>(q, k, s, NTOK, NTOK, DIM);

    // Softmax rows (scale folded in)
    softmax_rows_kernel<<<NTOK, thr>>>(s);

    // O = P V = P @ (V^T)^T  -> GEMM-NT with B = V^T [DIM, NTOK]
    gemm_nt_kernel<false><<<grid_proj, thr>>>(s, vt, out, NTOK, DIM, NTOK);
}

// round 4
// speedup vs baseline: 3.2477x; 3.2477x over previous
#include <cuda_runtime.h>
#include <math.h>
#include <stdint.h>

#define NTOK 4096
#define DIM  1024

// ---------------- scratch (__device__ globals; no allocation allowed) -------
__device__ float g_xr [NTOK * DIM];            // x  rounded to tf32
__device__ float g_wqr[DIM * DIM];
__device__ float g_wkr[DIM * DIM];
__device__ float g_wvr[DIM * DIM];
__device__ float g_q  [NTOK * DIM];            // Q (tf32-rounded)
__device__ float g_k  [NTOK * DIM];            // K (tf32-rounded)
__device__ float g_vt [DIM * NTOK];            // V^T (tf32-rounded)
__device__ float g_s  [(size_t)NTOK * NTOK];   // scores -> probs

// ---------------- helpers ---------------------------------------------------
__device__ __forceinline__ float tf32_rn(float x) {
    uint32_t u;
    asm("cvt.rna.tf32.f32 %0, %1;" : "=r"(u) : "f"(x));
    return __uint_as_float(u);
}

__device__ __forceinline__ void cp_async16(uint32_t dst_smem, const float* src) {
    asm volatile("cp.async.cg.shared.global [%0], [%1], 16;\n"
                 :: "r"(dst_smem), "l"(src));
}
__device__ __forceinline__ void cp_commit() {
    asm volatile("cp.async.commit_group;\n");
}
template <int N>
__device__ __forceinline__ void cp_wait() {
    asm volatile("cp.async.wait_group %0;\n" :: "n"(N));
}

__device__ __forceinline__ void mma_tf32(float* c, const uint32_t* a, const uint32_t* b) {
    asm volatile(
        "mma.sync.aligned.m16n8k8.row.col.f32.tf32.tf32.f32 "
        "{%0,%1,%2,%3}, {%4,%5,%6,%7}, {%8,%9}, {%0,%1,%2,%3};"
        : "+f"(c[0]), "+f"(c[1]), "+f"(c[2]), "+f"(c[3])
        : "r"(a[0]), "r"(a[1]), "r"(a[2]), "r"(a[3]), "r"(b[0]), "r"(b[1]));
}

// ---------------- elementwise tf32 rounding pass ----------------------------
__global__ __launch_bounds__(256)
void round_tf32_kernel(const float* __restrict__ in, float* __restrict__ out, int n4) {
    int i = blockIdx.x * 256 + threadIdx.x;
    if (i < n4) {
        float4 v = ((const float4*)in)[i];
        v.x = tf32_rn(v.x); v.y = tf32_rn(v.y);
        v.z = tf32_rn(v.z); v.w = tf32_rn(v.w);
        ((float4*)out)[i] = v;
    }
}

// ---------------------------------------------------------------------------
// TF32 tensor-core GEMM-NT: C[M,N] = A[M,K] @ B[N,K]^T
// Inputs must already be tf32-rounded (HW truncation then lossless).
// BM=BN=128, BK=16, 256 threads, warp tile 64x32, cp.async double buffer.
// LDS row stride 20 words -> (20g + t) mod 32 is a perfect bank permutation
// for both A and B fragment load patterns (conflict-free).
// ---------------------------------------------------------------------------
#define BM 128
#define BN 128
#define BK 16
#define LDSS 20   // words per smem row (16 used + 4 pad)

template <bool TRANS_OUT, bool ROUND_OUT>
__global__ __launch_bounds__(256, 2)
void gemm_tf32(const float* __restrict__ A,
               const float* __restrict__ B,
               float* __restrict__ C,
               int M, int N, int K)
{
    __shared__ float As[2][BM * LDSS];   // 10240 B per stage
    __shared__ float Bs[2][BN * LDSS];

    const int tid  = threadIdx.x;
    const int lane = tid & 31;
    const int warp = tid >> 5;
    const int wm = (warp & 1) * 64;      // warp M offset inside tile
    const int wn = (warp >> 1) * 32;     // warp N offset inside tile
    const int g  = lane >> 2;            // group id 0..7
    const int t  = lane & 3;             // thread-in-group 0..3

    const int m0 = blockIdx.y * BM;
    const int n0 = blockIdx.x * BN;

    // global->smem mapping: thread loads 2 float4 from A and 2 from B
    const int lr = tid >> 2;             // 0..63
    const int lc = (tid & 3) * 4;        // 0,4,8,12
    const float* Ag = A + (size_t)(m0 + lr) * K + lc;
    const float* Bg = B + (size_t)(n0 + lr) * K + lc;
    const uint32_t sA0 = (uint32_t)__cvta_generic_to_shared(&As[0][0]);
    const uint32_t sB0 = (uint32_t)__cvta_generic_to_shared(&Bs[0][0]);
    const uint32_t stageA = BM * LDSS * 4;   // bytes per stage
    const uint32_t dstA0 = sA0 + (lr * LDSS + lc) * 4;
    const uint32_t dstA1 = sA0 + ((lr + 64) * LDSS + lc) * 4;
    const uint32_t dstB0 = sB0 + (lr * LDSS + lc) * 4;
    const uint32_t dstB1 = sB0 + ((lr + 64) * LDSS + lc) * 4;

    float acc[4][4][4];
#pragma unroll
    for (int i = 0; i < 4; i++)
#pragma unroll
        for (int j = 0; j < 4; j++)
#pragma unroll
            for (int r = 0; r < 4; r++) acc[i][j][r] = 0.0f;

    const int KT = K / BK;

    // prologue: stage 0
    cp_async16(dstA0, Ag);
    cp_async16(dstA1, Ag + (size_t)64 * K);
    cp_async16(dstB0, Bg);
    cp_async16(dstB1, Bg + (size_t)64 * K);
    cp_commit();

    for (int kt = 0; kt < KT; kt++) {
        const int s = kt & 1;
        if (kt + 1 < KT) {
            const int k0 = (kt + 1) * BK;
            const uint32_t off = (s ^ 1) * stageA;
            cp_async16(dstA0 + off, Ag + k0);
            cp_async16(dstA1 + off, Ag + (size_t)64 * K + k0);
            cp_async16(dstB0 + off, Bg + k0);
            cp_async16(dstB1 + off, Bg + (size_t)64 * K + k0);
            cp_commit();
            cp_wait<1>();
        } else {
            cp_wait<0>();
        }
        __syncthreads();

        const float* Asb = &As[s][0];
        const float* Bsb = &Bs[s][0];
#pragma unroll
        for (int kk = 0; kk < BK; kk += 8) {
            uint32_t a[4][4], b[4][2];
#pragma unroll
            for (int mt = 0; mt < 4; mt++) {
                const float* p = Asb + (wm + mt * 16 + g) * LDSS + kk + t;
                a[mt][0] = __float_as_uint(p[0]);
                a[mt][1] = __float_as_uint(p[8 * LDSS]);
                a[mt][2] = __float_as_uint(p[4]);
                a[mt][3] = __float_as_uint(p[8 * LDSS + 4]);
            }
#pragma unroll
            for (int nt = 0; nt < 4; nt++) {
                const float* p = Bsb + (wn + nt * 8 + g) * LDSS + kk + t;
                b[nt][0] = __float_as_uint(p[0]);
                b[nt][1] = __float_as_uint(p[4]);
            }
#pragma unroll
            for (int mt = 0; mt < 4; mt++)
#pragma unroll
                for (int nt = 0; nt < 4; nt++)
                    mma_tf32(acc[mt][nt], a[mt], b[nt]);
        }
        __syncthreads();   // WAR: next cp.async overwrites this stage
    }

    // epilogue
#pragma unroll
    for (int mt = 0; mt < 4; mt++) {
#pragma unroll
        for (int nt = 0; nt < 4; nt++) {
            float v0 = acc[mt][nt][0], v1 = acc[mt][nt][1];
            float v2 = acc[mt][nt][2], v3 = acc[mt][nt][3];
            if (ROUND_OUT) {
                v0 = tf32_rn(v0); v1 = tf32_rn(v1);
                v2 = tf32_rn(v2); v3 = tf32_rn(v3);
            }
            const int r = m0 + wm + mt * 16 + g;
            const int c = n0 + wn + nt * 8 + 2 * t;
            if (TRANS_OUT) {
                C[(size_t)c * M + r]           = v0;
                C[(size_t)(c + 1) * M + r]     = v1;
                C[(size_t)c * M + r + 8]       = v2;
                C[(size_t)(c + 1) * M + r + 8] = v3;
            } else {
                *(float2*)&C[(size_t)r * N + c]       = make_float2(v0, v1);
                *(float2*)&C[(size_t)(r + 8) * N + c] = make_float2(v2, v3);
            }
        }
    }
}

// ---------------------------------------------------------------------------
// Row softmax (scale 1/32 folded in), output rounded to tf32 for the PV GEMM.
// ---------------------------------------------------------------------------
__global__ __launch_bounds__(256)
void softmax_rows_kernel(float* __restrict__ S)
{
    const int row = blockIdx.x;
    float* p = S + (size_t)row * NTOK;
    const int tid = threadIdx.x;
    __shared__ float red[256];

    float m = -INFINITY;
    for (int i = tid; i < NTOK; i += 256) m = fmaxf(m, p[i]);
    red[tid] = m;
    __syncthreads();
    for (int s = 128; s > 0; s >>= 1) {
        if (tid < s) red[tid] = fmaxf(red[tid], red[tid + s]);
        __syncthreads();
    }
    m = red[0];
    __syncthreads();

    const float scale = 0.03125f;   // 1/sqrt(1024)
    float sum = 0.0f;
    for (int i = tid; i < NTOK; i += 256) {
        float e = __expf((p[i] - m) * scale);
        p[i] = e;
        sum += e;
    }
    red[tid] = sum;
    __syncthreads();
    for (int s = 128; s > 0; s >>= 1) {
        if (tid < s) red[tid] += red[tid + s];
        __syncthreads();
    }
    const float inv = 1.0f / red[0];
    __syncthreads();

    for (int i = tid; i < NTOK; i += 256) p[i] = tf32_rn(p[i] * inv);
}

// ---------------------------------------------------------------------------
extern "C" void kernel_launch(void* const* d_in, const int* in_sizes, int n_in,
                              void* d_out, int out_size)
{
    const float* x  = (const float*)d_in[0];
    const float* wq = (const float*)d_in[1];
    const float* wk = (const float*)d_in[2];
    const float* wv = (const float*)d_in[3];
    float* out = (float*)d_out;

    float *xr, *wqr, *wkr, *wvr, *q, *k, *vt, *s;
    cudaGetSymbolAddress((void**)&xr,  g_xr);
    cudaGetSymbolAddress((void**)&wqr, g_wqr);
    cudaGetSymbolAddress((void**)&wkr, g_wkr);
    cudaGetSymbolAddress((void**)&wvr, g_wvr);
    cudaGetSymbolAddress((void**)&q,   g_q);
    cudaGetSymbolAddress((void**)&k,   g_k);
    cudaGetSymbolAddress((void**)&vt,  g_vt);
    cudaGetSymbolAddress((void**)&s,   g_s);

    // round inputs to nearest-tf32 (HW mma truncation then lossless)
    {
        int nx4 = NTOK * DIM / 4, nw4 = DIM * DIM / 4;
        round_tf32_kernel<<<(nx4 + 255) / 256, 256>>>(x,  xr,  nx4);
        round_tf32_kernel<<<(nw4 + 255) / 256, 256>>>(wq, wqr, nw4);
        round_tf32_kernel<<<(nw4 + 255) / 256, 256>>>(wk, wkr, nw4);
        round_tf32_kernel<<<(nw4 + 255) / 256, 256>>>(wv, wvr, nw4);
    }

    dim3 thr(256);
    dim3 grid_proj(DIM / BN, NTOK / BM);    // (8, 32)
    dim3 grid_sc(NTOK / BN, NTOK / BM);     // (32, 32)

    // projections (outputs rounded to tf32 for the next GEMM)
    gemm_tf32<false, true><<<grid_proj, thr>>>(xr, wqr, q,  NTOK, DIM, DIM);
    gemm_tf32<false, true><<<grid_proj, thr>>>(xr, wkr, k,  NTOK, DIM, DIM);
    gemm_tf32<true,  true><<<grid_proj, thr>>>(xr, wvr, vt, NTOK, DIM, DIM);

    // scores S = Q K^T (softmax next; its output gets rounded there)
    gemm_tf32<false, false><<<grid_sc, thr>>>(q, k, s, NTOK, NTOK, DIM);

    softmax_rows_kernel<<<NTOK, thr>>>(s);

    // O = P @ (V^T)^T  (final output stays full f32)
    gemm_tf32<false, false><<<grid_proj, thr>>>(s, vt, out, NTOK, DIM, NTOK);
}

// round 9
// speedup vs baseline: 3.8035x; 1.1711x over previous
#include <cuda_runtime.h>
#include <math.h>
#include <stdint.h>

#define NTOK 4096
#define DIM  1024

// ---------------- scratch (__device__ globals; no allocation allowed) -------
__device__ float g_xr [NTOK * DIM];
__device__ float g_wqr[DIM * DIM];
__device__ float g_wkr[DIM * DIM];
__device__ float g_wvr[DIM * DIM];
__device__ float g_q  [NTOK * DIM];
__device__ float g_k  [NTOK * DIM];
__device__ float g_vt [DIM * NTOK];
__device__ float g_s  [(size_t)NTOK * NTOK];

// ---------------- helpers ---------------------------------------------------
__device__ __forceinline__ float tf32_rn(float x) {
    uint32_t u;
    asm("cvt.rna.tf32.f32 %0, %1;" : "=r"(u) : "f"(x));
    return __uint_as_float(u);
}
__device__ __forceinline__ void cp_async16(uint32_t dst, const float* src) {
    asm volatile("cp.async.cg.shared.global [%0], [%1], 16;\n" :: "r"(dst), "l"(src));
}
__device__ __forceinline__ void cp_commit() {
    asm volatile("cp.async.commit_group;\n");
}
template <int N>
__device__ __forceinline__ void cp_wait() {
    asm volatile("cp.async.wait_group %0;\n" :: "n"(N));
}
__device__ __forceinline__ void mma_tf32(float* c, const uint32_t* a, const uint32_t* b) {
    asm volatile(
        "mma.sync.aligned.m16n8k8.row.col.f32.tf32.tf32.f32 "
        "{%0,%1,%2,%3}, {%4,%5,%6,%7}, {%8,%9}, {%0,%1,%2,%3};"
        : "+f"(c[0]), "+f"(c[1]), "+f"(c[2]), "+f"(c[3])
        : "r"(a[0]), "r"(a[1]), "r"(a[2]), "r"(a[3]), "r"(b[0]), "r"(b[1]));
}

// ---------------- elementwise tf32 rounding pass ----------------------------
__global__ __launch_bounds__(256)
void round_tf32_kernel(const float* __restrict__ in, float* __restrict__ out, int n4) {
    int i = blockIdx.x * 256 + threadIdx.x;
    if (i < n4) {
        float4 v = ((const float4*)in)[i];
        v.x = tf32_rn(v.x); v.y = tf32_rn(v.y);
        v.z = tf32_rn(v.z); v.w = tf32_rn(v.w);
        ((float4*)out)[i] = v;
    }
}

// ---------------------------------------------------------------------------
// TF32 mma.sync GEMM-NT: C[M,N] = A[M,K] @ B[N,K]^T
// CTA tile 128x128, BK=32, 256 threads, warp tile 64x32.
// 4-stage cp.async ring, prefetch distance 2, ONE __syncthreads per K-slab.
// Smem row stride 36 words: bank = (36g+t)%32 = (4g+t)%32, perfect permutation.
// Register double-buffered fragments across the four k8 steps.
// ---------------------------------------------------------------------------
#define LDSS 36                      // words per smem row (32 used + 4 pad)
#define OPER_FLOATS (128 * LDSS)     // 4608 floats per operand per stage
#define STAGE_FLOATS (2 * OPER_FLOATS)
#define STAGE_BYTES  (STAGE_FLOATS * 4)          // 36864
#define DYN_BYTES    (4 * STAGE_BYTES)           // 147456

extern __shared__ float smem_dyn[];

template <bool TRANS_OUT, bool ROUND_OUT>
__global__ __launch_bounds__(256, 1)
void gemm_tf32(const float* __restrict__ A,
               const float* __restrict__ B,
               float* __restrict__ C,
               int M, int N, int K)
{
    const int tid  = threadIdx.x;
    const int lane = tid & 31;
    const int warp = tid >> 5;
    const int wm = (warp & 1) * 64;
    const int wn = (warp >> 1) * 32;
    const int g  = lane >> 2;
    const int t  = lane & 3;

    const int m0 = blockIdx.y * 128;
    const int n0 = blockIdx.x * 128;

    // ---- global->smem mapping: 4 float4 per thread per operand per stage ---
    const int lr = tid >> 3;             // 0..31
    const int lc = (tid & 7) * 4;        // 0..28
    const float* Abase = A + (size_t)(m0 + lr) * K + lc;
    const float* Bbase = B + (size_t)(n0 + lr) * K + lc;
    const uint32_t s0 = (uint32_t)__cvta_generic_to_shared(smem_dyn);
    const uint32_t dA = s0 + (uint32_t)((lr * LDSS + lc) * 4);
    const uint32_t dB = dA + OPER_FLOATS * 4;

    float acc[4][4][4];
#pragma unroll
    for (int i = 0; i < 4; i++)
#pragma unroll
        for (int j = 0; j < 4; j++)
#pragma unroll
            for (int r = 0; r < 4; r++) acc[i][j][r] = 0.0f;

    const int KT = K >> 5;               // 32-wide K slabs

#define FILL_STAGE(S, K0)                                                  \
    do {                                                                   \
        const uint32_t o = (uint32_t)(S) * STAGE_BYTES;                    \
        _Pragma("unroll")                                                  \
        for (int i = 0; i < 4; i++) {                                      \
            cp_async16(dA + o + i * (32 * LDSS * 4),                       \
                       Abase + (K0) + (size_t)(32 * i) * K);               \
            cp_async16(dB + o + i * (32 * LDSS * 4),                       \
                       Bbase + (K0) + (size_t)(32 * i) * K);               \
        }                                                                  \
    } while (0)

    // prologue: stages 0,1
    FILL_STAGE(0, 0);
    cp_commit();
    FILL_STAGE(1, 32);
    cp_commit();

    for (int kt = 0; kt < KT; kt++) {
        const int s = kt & 3;
        if (kt + 2 < KT) FILL_STAGE((kt + 2) & 3, (kt + 2) << 5);
        cp_commit();
        cp_wait<2>();
        __syncthreads();

        const float* As = smem_dyn + (size_t)s * STAGE_FLOATS;
        const float* Bs = As + OPER_FLOATS;
        const float* ap = As + (wm + g) * LDSS + t;
        const float* bp = Bs + (wn + g) * LDSS + t;

        uint32_t a[2][4][4], b[2][4][2];

#define LOAD_FRAG(BUF, KK)                                                 \
    do {                                                                   \
        _Pragma("unroll")                                                  \
        for (int mt = 0; mt < 4; mt++) {                                   \
            const float* p = ap + mt * (16 * LDSS) + (KK) * 8;             \
            a[BUF][mt][0] = __float_as_uint(p[0]);                         \
            a[BUF][mt][1] = __float_as_uint(p[8 * LDSS]);                  \
            a[BUF][mt][2] = __float_as_uint(p[4]);                         \
            a[BUF][mt][3] = __float_as_uint(p[8 * LDSS + 4]);              \
        }                                                                  \
        _Pragma("unroll")                                                  \
        for (int nt = 0; nt < 4; nt++) {                                   \
            const float* p = bp + nt * (8 * LDSS) + (KK) * 8;              \
            b[BUF][nt][0] = __float_as_uint(p[0]);                         \
            b[BUF][nt][1] = __float_as_uint(p[4]);                         \
        }                                                                  \
    } while (0)

        LOAD_FRAG(0, 0);
#pragma unroll
        for (int kk = 0; kk < 4; kk++) {
            if (kk < 3) LOAD_FRAG((kk + 1) & 1, kk + 1);
            const int cb = kk & 1;
#pragma unroll
            for (int mt = 0; mt < 4; mt++)
#pragma unroll
                for (int nt = 0; nt < 4; nt++)
                    mma_tf32(acc[mt][nt], a[cb][mt], b[cb][nt]);
        }
#undef LOAD_FRAG
    }
#undef FILL_STAGE

    // ---- epilogue ----
#pragma unroll
    for (int mt = 0; mt < 4; mt++) {
#pragma unroll
        for (int nt = 0; nt < 4; nt++) {
            float v0 = acc[mt][nt][0], v1 = acc[mt][nt][1];
            float v2 = acc[mt][nt][2], v3 = acc[mt][nt][3];
            if (ROUND_OUT) {
                v0 = tf32_rn(v0); v1 = tf32_rn(v1);
                v2 = tf32_rn(v2); v3 = tf32_rn(v3);
            }
            const int r = m0 + wm + mt * 16 + g;
            const int c = n0 + wn + nt * 8 + 2 * t;
            if (TRANS_OUT) {
                C[(size_t)c * M + r]           = v0;
                C[(size_t)(c + 1) * M + r]     = v1;
                C[(size_t)c * M + r + 8]       = v2;
                C[(size_t)(c + 1) * M + r + 8] = v3;
            } else {
                *(float2*)&C[(size_t)r * N + c]       = make_float2(v0, v1);
                *(float2*)&C[(size_t)(r + 8) * N + c] = make_float2(v2, v3);
            }
        }
    }
}

// ---------------------------------------------------------------------------
// Smem-resident row softmax (scale 1/32 folded in), output rounded to tf32.
// One global read + one global write per element.
// ---------------------------------------------------------------------------
__global__ __launch_bounds__(256)
void softmax_rows_kernel(float* __restrict__ S)
{
    __shared__ float buf[NTOK];          // 16 KB row cache
    __shared__ float red[8];

    const int row = blockIdx.x;
    const int tid = threadIdx.x;
    const int lane = tid & 31;
    const int wrp  = tid >> 5;
    float* p = S + (size_t)row * NTOK;

    // load row (float4)
    float4* b4 = (float4*)buf;
    const float4* in4 = (const float4*)p;
    float4* out4 = (float4*)p;
#pragma unroll
    for (int i = 0; i < 4; i++) b4[tid + i * 256] = in4[tid + i * 256];
    __syncthreads();

    // max
    float m = -INFINITY;
#pragma unroll
    for (int i = 0; i < 16; i++) m = fmaxf(m, buf[tid + i * 256]);
#pragma unroll
    for (int o = 16; o > 0; o >>= 1) m = fmaxf(m, __shfl_xor_sync(~0u, m, o));
    if (lane == 0) red[wrp] = m;
    __syncthreads();
    m = red[0];
#pragma unroll
    for (int w = 1; w < 8; w++) m = fmaxf(m, red[w]);

    // exp + sum
    const float scale = 0.03125f;        // 1/sqrt(1024)
    float sum = 0.0f;
#pragma unroll
    for (int i = 0; i < 16; i++) {
        float e = __expf((buf[tid + i * 256] - m) * scale);
        buf[tid + i * 256] = e;
        sum += e;
    }
#pragma unroll
    for (int o = 16; o > 0; o >>= 1) sum += __shfl_xor_sync(~0u, sum, o);
    __syncthreads();                     // red[] reuse
    if (lane == 0) red[wrp] = sum;
    __syncthreads();
    sum = 0.0f;
#pragma unroll
    for (int w = 0; w < 8; w++) sum += red[w];
    const float inv = 1.0f / sum;

    // normalize + round + store
#pragma unroll
    for (int i = 0; i < 4; i++) {
        float4 v = b4[tid + i * 256];
        v.x = tf32_rn(v.x * inv); v.y = tf32_rn(v.y * inv);
        v.z = tf32_rn(v.z * inv); v.w = tf32_rn(v.w * inv);
        out4[tid + i * 256] = v;
    }
}

// ---------------------------------------------------------------------------
extern "C" void kernel_launch(void* const* d_in, const int* in_sizes, int n_in,
                              void* d_out, int out_size)
{
    const float* x  = (const float*)d_in[0];
    const float* wq = (const float*)d_in[1];
    const float* wk = (const float*)d_in[2];
    const float* wv = (const float*)d_in[3];
    float* out = (float*)d_out;

    float *xr, *wqr, *wkr, *wvr, *q, *k, *vt, *s;
    cudaGetSymbolAddress((void**)&xr,  g_xr);
    cudaGetSymbolAddress((void**)&wqr, g_wqr);
    cudaGetSymbolAddress((void**)&wkr, g_wkr);
    cudaGetSymbolAddress((void**)&wvr, g_wvr);
    cudaGetSymbolAddress((void**)&q,   g_q);
    cudaGetSymbolAddress((void**)&k,   g_k);
    cudaGetSymbolAddress((void**)&vt,  g_vt);
    cudaGetSymbolAddress((void**)&s,   g_s);

    cudaFuncSetAttribute(gemm_tf32<false, true >, cudaFuncAttributeMaxDynamicSharedMemorySize, DYN_BYTES);
    cudaFuncSetAttribute(gemm_tf32<true,  true >, cudaFuncAttributeMaxDynamicSharedMemorySize, DYN_BYTES);
    cudaFuncSetAttribute(gemm_tf32<false, false>, cudaFuncAttributeMaxDynamicSharedMemorySize, DYN_BYTES);

    // round inputs to nearest-tf32 (HW mma truncation then lossless)
    {
        int nx4 = NTOK * DIM / 4, nw4 = DIM * DIM / 4;
        round_tf32_kernel<<<(nx4 + 255) / 256, 256>>>(x,  xr,  nx4);
        round_tf32_kernel<<<(nw4 + 255) / 256, 256>>>(wq, wqr, nw4);
        round_tf32_kernel<<<(nw4 + 255) / 256, 256>>>(wk, wkr, nw4);
        round_tf32_kernel<<<(nw4 + 255) / 256, 256>>>(wv, wvr, nw4);
    }

    dim3 thr(256);
    dim3 grid_proj(DIM / 128, NTOK / 128);    // (8, 32)
    dim3 grid_sc(NTOK / 128, NTOK / 128);     // (32, 32)

    gemm_tf32<false, true ><<<grid_proj, thr, DYN_BYTES>>>(xr, wqr, q,  NTOK, DIM, DIM);
    gemm_tf32<false, true ><<<grid_proj, thr, DYN_BYTES>>>(xr, wkr, k,  NTOK, DIM, DIM);
    gemm_tf32<true,  true ><<<grid_proj, thr, DYN_BYTES>>>(xr, wvr, vt, NTOK, DIM, DIM);

    gemm_tf32<false, false><<<grid_sc, thr, DYN_BYTES>>>(q, k, s, NTOK, NTOK, DIM);

    softmax_rows_kernel<<<NTOK, thr>>>(s);

    gemm_tf32<false, false><<<grid_proj, thr, DYN_BYTES>>>(s, vt, out, NTOK, DIM, NTOK);
}